// round 17
// baseline (speedup 1.0000x reference)
#include <cuda_runtime.h>
#include <math.h>
#include <stdint.h>

// ---------------- problem constants ----------------
#define NPIX   1024          // 32*32
#define C_MID  512
#define KTOT   2304          // 256*9
#define KSPLIT 4
#define KPER   (KTOT / KSPLIT)   // 576
#define NBOX   9216          // 1024*9
#define NW     144           // NBOX/64
#define IOU_THR 0.7f

// ---------------- static device scratch ----------------
__device__ float g_wt[KTOT * C_MID];                 // conv1 weights transposed [k][co]
__device__ float g_col[KTOT * NPIX];                 // im2col [k][p]
__device__ float g_hp[KSPLIT * NPIX * C_MID];        // split-K partial activations
__device__ float g_boxes[NBOX * 4];
__device__ float g_scores[NBOX];
__device__ __align__(16) unsigned long long g_key[NBOX];
__device__ int g_order[NBOX];
__device__ float4 g_bsorted[NBOX];
__device__ unsigned long long g_mask[(size_t)NBOX * NW];
__device__ unsigned long long g_keepmask[NW];
__device__ int g_V;

// anchors: a = size_idx*3 + ratio_idx, sizes {32,64,128}, ratios {.5,1,2}
__constant__ float c_aw[9] = {
    45.254833995939045f, 32.0f, 22.627416997969522f,
    90.50966799187809f,  64.0f, 45.254833995939045f,
    181.01933598375618f, 128.0f, 90.50966799187809f };
__constant__ float c_ah[9] = {
    22.627416997969522f, 32.0f, 45.254833995939045f,
    45.254833995939045f, 64.0f, 90.50966799187809f,
    90.50966799187809f,  128.0f, 181.01933598375618f };

// ---------------- packed f32x2 helpers (sm_103a) ----------------
__device__ __forceinline__ void ffma2(unsigned long long& acc, unsigned long long a, unsigned long long b) {
    asm("fma.rn.f32x2 %0, %1, %2, %0;" : "+l"(acc) : "l"(a), "l"(b));
}
__device__ __forceinline__ unsigned long long dup2(float x) {
    unsigned long long r;
    asm("mov.b64 %0, {%1, %1};" : "=l"(r) : "f"(x));
    return r;
}
__device__ __forceinline__ void unpack2(unsigned long long v, float& lo, float& hi) {
    asm("mov.b64 {%0, %1}, %2;" : "=f"(lo), "=f"(hi) : "l"(v));
}

// ---------------- K0: prep (296 grid-stride blocks, single wave) ----------------
// transpose w1 [512][2304] -> g_wt [2304][512], im2col -> g_col, reset g_V
#define PREP_BLOCKS 296
__global__ void __launch_bounds__(256) k_prep(const float* __restrict__ w, const float* __restrict__ feat) {
    const int bid = blockIdx.x;
    const int t = threadIdx.x;
    __shared__ float tile[32][33];
    // transpose: 1152 tiles, ~4 per block
    for (int tid0 = bid; tid0 < 1152; tid0 += PREP_BLOCKS) {
        int kb = (tid0 % 72) * 32, cb = (tid0 / 72) * 32;
        int tx = t & 31, ty = t >> 5;           // 32 x 8
        __syncthreads();
        for (int i = ty; i < 32; i += 8)
            tile[i][tx] = w[(cb + i) * KTOT + kb + tx];
        __syncthreads();
        for (int i = ty; i < 32; i += 8)
            g_wt[(kb + i) * C_MID + cb + tx] = tile[tx][i];
    }
    // im2col: 2304*1024 floats = 589824 float4, ~8 per thread
    for (int e4 = bid * 256 + t; e4 < KTOT * 256; e4 += PREP_BLOCKS * 256) {
        int k = e4 >> 8, pq = e4 & 255;
        int p0 = pq * 4;
        int c = k / 9, tt = k - c * 9;
        int dy = tt / 3, dx = tt % 3;
        int y = (p0 >> 5) + dy - 1;             // same row for all 4 lanes
        int xb = (p0 & 31) + dx - 1;
        float4 v = make_float4(0, 0, 0, 0);
        if ((unsigned)y < 32u) {
            const float* row = &feat[c * NPIX + y * 32];
            if ((unsigned)(xb + 0) < 32u) v.x = row[xb + 0];
            if ((unsigned)(xb + 1) < 32u) v.y = row[xb + 1];
            if ((unsigned)(xb + 2) < 32u) v.z = row[xb + 2];
            if ((unsigned)(xb + 3) < 32u) v.w = row[xb + 3];
        }
        *(float4*)&g_col[(size_t)k * NPIX + p0] = v;
    }
    if (bid == 0 && t == 0) g_V = 0;
}

// ---------------- K2: SGEMM 1024x512x2304, split-K x4, f32x2 (R14 proven config) --------
// tile: 128 px x 128 co, 256 threads, 8x8 per thread
__global__ void __launch_bounds__(256) k_gemm() {
    __shared__ float As[32][128];
    __shared__ float Bs[32][128];
    const int tx = threadIdx.x & 15;      // co group
    const int ty = threadIdx.x >> 4;      // pixel group
    const int co0 = blockIdx.x * 128;
    const int p0  = blockIdx.y * 128;
    const int kz  = blockIdx.z;

    unsigned long long acc[8][4];
#pragma unroll
    for (int i = 0; i < 8; i++)
#pragma unroll
        for (int j = 0; j < 4; j++) acc[i][j] = 0ull;

    const int kbeg = kz * KPER;
    for (int k0 = kbeg; k0 < kbeg + KPER; k0 += 32) {
#pragma unroll
        for (int i = 0; i < 4; i++) {
            int idx = threadIdx.x + i * 256;          // 0..1023 float4 slots
            int kk = idx >> 5, q = idx & 31;
            *(float4*)&As[kk][q * 4] = *(const float4*)&g_col[(size_t)(k0 + kk) * NPIX + p0 + q * 4];
            *(float4*)&Bs[kk][q * 4] = *(const float4*)&g_wt[(size_t)(k0 + kk) * C_MID + co0 + q * 4];
        }
        __syncthreads();
#pragma unroll
        for (int kk = 0; kk < 32; kk++) {
            float4 a0 = *(const float4*)&As[kk][ty * 8];
            float4 a1 = *(const float4*)&As[kk][ty * 8 + 4];
            ulonglong2 bq = *(const ulonglong2*)&Bs[kk][tx * 8];
            ulonglong2 br = *(const ulonglong2*)&Bs[kk][tx * 8 + 4];
            float av[8] = {a0.x, a0.y, a0.z, a0.w, a1.x, a1.y, a1.z, a1.w};
#pragma unroll
            for (int i = 0; i < 8; i++) {
                unsigned long long ai = dup2(av[i]);
                ffma2(acc[i][0], ai, bq.x);
                ffma2(acc[i][1], ai, bq.y);
                ffma2(acc[i][2], ai, br.x);
                ffma2(acc[i][3], ai, br.y);
            }
        }
        __syncthreads();
    }
    float* outb = &g_hp[(size_t)kz * NPIX * C_MID];
#pragma unroll
    for (int i = 0; i < 8; i++) {
        int p = p0 + ty * 8 + i;
        float v[8];
#pragma unroll
        for (int j = 0; j < 4; j++) unpack2(acc[i][j], v[2 * j], v[2 * j + 1]);
        float* dst = &outb[(size_t)p * C_MID + co0 + tx * 8];
        *(float4*)dst       = make_float4(v[0], v[1], v[2], v[3]);
        *(float4*)(dst + 4) = make_float4(v[4], v[5], v[6], v[7]);
    }
}

// ---------------- K3: combine + bias + relu, heads (8 px/block), decode, keys, V ------
__global__ void __launch_bounds__(256) k_heads(const float* __restrict__ b1,
                                               const float* __restrict__ w2, const float* __restrict__ b2,
                                               const float* __restrict__ w3, const float* __restrict__ b3) {
    __shared__ float hsm[8][512];
    __shared__ float res[8][48];
    __shared__ int bcnt;
    const int p0 = blockIdx.x * 8;
    const int tid = threadIdx.x, lane = tid & 31, warp = tid >> 5;
    if (tid == 0) bcnt = 0;

    for (int e = tid; e < 8 * 128; e += 256) {
        int px = e >> 7, cq = e & 127;
        size_t off = (size_t)(p0 + px) * C_MID + cq * 4;
        float4 s = *(const float4*)&g_hp[off];
#pragma unroll
        for (int sk = 1; sk < KSPLIT; sk++) {
            float4 q = *(const float4*)&g_hp[(size_t)sk * NPIX * C_MID + off];
            s.x += q.x; s.y += q.y; s.z += q.z; s.w += q.w;
        }
        float4 bb = *(const float4*)&b1[cq * 4];
        hsm[px][cq * 4 + 0] = fmaxf(s.x + bb.x, 0.0f);
        hsm[px][cq * 4 + 1] = fmaxf(s.y + bb.y, 0.0f);
        hsm[px][cq * 4 + 2] = fmaxf(s.z + bb.z, 0.0f);
        hsm[px][cq * 4 + 3] = fmaxf(s.w + bb.w, 0.0f);
    }
    __syncthreads();

    for (int o = warp; o < 45; o += 8) {
        const float* wr; float bv;
        if (o < 9) { wr = w2 + o * 512; bv = b2[o]; }
        else       { wr = w3 + (o - 9) * 512; bv = b3[o - 9]; }
        float acc[8] = {0, 0, 0, 0, 0, 0, 0, 0};
#pragma unroll 4
        for (int c = lane; c < 512; c += 32) {
            float wv = wr[c];
#pragma unroll
            for (int px = 0; px < 8; px++) acc[px] += hsm[px][c] * wv;
        }
#pragma unroll
        for (int px = 0; px < 8; px++) {
#pragma unroll
            for (int s = 16; s; s >>= 1) acc[px] += __shfl_xor_sync(0xffffffffu, acc[px], s);
            if (lane == 0) res[px][o] = acc[px] + bv;
        }
    }
    __syncthreads();

    if (tid < 72) {
        const int pxl = tid / 9, a = tid % 9;
        const int p = p0 + pxl;
        float logit = res[pxl][a];
        float score = 1.0f / (1.0f + expf(-logit));
        float o0 = res[pxl][9 + a * 4 + 0];
        float o1 = res[pxl][9 + a * 4 + 1];
        float o2 = res[pxl][9 + a * 4 + 2];
        float o3 = res[pxl][9 + a * 4 + 3];
        int y = p >> 5, x = p & 31;
        float acx = ((float)x + 0.5f) * 16.0f;
        float acy = ((float)y + 0.5f) * 16.0f;
        float aw = c_aw[a], ah = c_ah[a];
        float cx = acx + o0 * aw;
        float cy = acy + o1 * ah;
        float bw = aw * expf(o2);
        float bh = ah * expf(o3);
        float x1 = fminf(fmaxf(cx - bw * 0.5f, 0.0f), 512.0f);
        float y1 = fminf(fmaxf(cy - bh * 0.5f, 0.0f), 512.0f);
        float x2 = fminf(fmaxf(cx + bw * 0.5f, 0.0f), 512.0f);
        float y2 = fminf(fmaxf(cy + bh * 0.5f, 0.0f), 512.0f);
        bool valid = (x2 - x1 >= 0.001f) && (y2 - y1 >= 0.001f) && (score >= 0.5f);
        int i = p * 9 + a;
        g_boxes[i * 4 + 0] = x1;
        g_boxes[i * 4 + 1] = y1;
        g_boxes[i * 4 + 2] = x2;
        g_boxes[i * 4 + 3] = y2;
        g_scores[i] = score;
        if (valid) atomicAdd(&bcnt, 1);
        float seff = valid ? score : -INFINITY;
        unsigned int b = __float_as_uint(seff);
        unsigned int u = (b & 0x80000000u) ? ~b : (b | 0x80000000u); // ascending
        unsigned int d = ~u;                                         // descending
        g_key[i] = ((unsigned long long)d << 32) | (unsigned int)i;  // tie: idx asc
    }
    __syncthreads();
    if (tid == 0 && bcnt) atomicAdd(&g_V, bcnt);
}

// ---------------- K4: block-local rank + scatter (144 blocks own 64 items each) --------
__global__ void __launch_bounds__(256) k_rank() {
    __shared__ ulonglong2 sT[512];              // 8 KB
    __shared__ int rsum[64];
    const int bid = blockIdx.x;
    const int t = threadIdx.x;
    const int il = t & 63;                      // item local
    const int seg = t >> 6;                     // 0..3 key segments
    const int item = bid * 64 + il;
    const unsigned long long ki = g_key[item];
    const ulonglong2* kk2 = (const ulonglong2*)g_key;
    int cnt = 0;
    if (t < 64) rsum[t] = 0;
    for (int step = 0; step < 9; step++) {
        __syncthreads();
        {
            int i1 = t, i2 = t + 256;
            sT[i1] = kk2[(i1 >> 7) * 1152 + step * 128 + (i1 & 127)];
            sT[i2] = kk2[(i2 >> 7) * 1152 + step * 128 + (i2 & 127)];
        }
        __syncthreads();
        const int sb = seg * 128;
#pragma unroll 8
        for (int j = 0; j < 128; j++) {
            ulonglong2 v = sT[sb + j];
            cnt += (v.x < ki) ? 1 : 0;
            cnt += (v.y < ki) ? 1 : 0;
        }
    }
    __syncthreads();
    atomicAdd(&rsum[il], cnt);
    __syncthreads();
    if (t < 64) {
        int r = rsum[t];
        int it2 = bid * 64 + t;
        g_order[r] = it2;
        g_bsorted[r] = *(const float4*)&g_boxes[it2 * 4];
    }
}

// ---------------- K5: pairwise IoU bitmask (144 row-chunk blocks, 1 wave) ----------------
__global__ void __launch_bounds__(256) k_mask() {
    const int V = g_V;
    const int NC = (V + 63) >> 6;
    const int rc = blockIdx.x;
    if (rc >= NC) return;
    __shared__ float4 cb[4][64];
    const int t = threadIdx.x;
    const int wl = t >> 6;
    const int rl = t & 63;
    const int i = rc * 64 + rl;
    float4 bi = (i < V) ? g_bsorted[i] : make_float4(0, 0, 0, 0);
    float areai = (bi.z - bi.x) * (bi.w - bi.y);
    const int ng = NC - rc;
    const int nu = (ng + 3) >> 2;
    for (int u = 0; u < nu; u++) {
        int s = u * 4 + wl;
        int cc = rc + s;
        bool act = (s < ng);
        __syncthreads();
        if (act) cb[wl][rl] = g_bsorted[cc * 64 + rl];
        __syncthreads();
        if (act && i < V) {
            unsigned long long bits = 0;
            int jmax = min(64, V - cc * 64);
            for (int jj = 0; jj < jmax; jj++) {
                int j = cc * 64 + jj;
                float4 bj = cb[wl][jj];
                float ix1 = fmaxf(bi.x, bj.x);
                float iy1 = fmaxf(bi.y, bj.y);
                float ix2 = fminf(bi.z, bj.z);
                float iy2 = fminf(bi.w, bj.w);
                float inter = fmaxf(ix2 - ix1, 0.0f) * fmaxf(iy2 - iy1, 0.0f);
                float uni = areai + (bj.z - bj.x) * (bj.w - bj.y) - inter;
                float iou = inter / fmaxf(uni, 1e-9f);
                unsigned long long hit = (iou > IOU_THR && j > i) ? 1ull : 0ull;
                bits |= hit << jj;
            }
            g_mask[(size_t)i * NW + cc] = bits;
        }
    }
}

// ---------------- K6: serial greedy NMS; ffs-over-candidates scan ----------------
__global__ void __launch_bounds__(256) k_nms() {
    __shared__ unsigned long long supp[NW];
    __shared__ unsigned long long keepm[NW];
    __shared__ unsigned long long dbuf[2][64];
    __shared__ unsigned long long s_km;
    const int t = threadIdx.x;
    for (int w = t; w < NW; w += 256) { supp[w] = 0ull; keepm[w] = 0ull; }
    const int V = g_V;
    const int NC = (V + 63) >> 6;
    if (t < 64) dbuf[0][t] = (t < V) ? g_mask[(size_t)t * NW + 0] : 0ull;
    __syncthreads();
    for (int c = 0; c < NC; c++) {
        if (t == 0) {
            const unsigned long long* rb = dbuf[c & 1];
            const int limit = min(64, V - c * 64);
            unsigned long long lm = (limit == 64) ? ~0ull : ((1ull << limit) - 1ull);
            unsigned long long cand = ~supp[c] & lm;   // unsuppressed, in range
            unsigned long long km = 0ull;
            while (cand) {
                int b = __ffsll((long long)cand) - 1;  // lowest surviving = kept
                km |= 1ull << b;
                cand &= ~(rb[b] | (1ull << b));        // drop it + everything it suppresses
            }
            keepm[c] = km;
            s_km = km;
        }
        __syncthreads();
        const unsigned long long km = s_km;
        if (t >= 64 && t < 128) {                      // prefetch next diag rows
            int b = t - 64, nc1 = c + 1;
            if (nc1 < NC) {
                int row = nc1 * 64 + b;
                dbuf[nc1 & 1][b] = (row < V) ? g_mask[(size_t)row * NW + nc1] : 0ull;
            }
        }
        if (km) {
            const unsigned long long* rowbase = &g_mask[(size_t)(c * 64) * NW];
            for (int w = c + 1 + t; w < NC; w += 256) {
                unsigned long long acc = 0ull;
#pragma unroll
                for (int b = 0; b < 64; b++) {
                    unsigned long long m = 0ull - ((km >> b) & 1ull);
                    acc |= rowbase[(size_t)b * NW + w] & m;
                }
                supp[w] |= acc;
            }
        }
        __syncthreads();
    }
    for (int w = t; w < NW; w += 256) g_keepmask[w] = keepm[w];
}

// ---------------- K7: write output (N,5) ----------------
__global__ void k_out(float* __restrict__ out) {
    int p = blockIdx.x * 256 + threadIdx.x;   // sorted position, exactly 9216
    int V = g_V;
    bool keep = (p < V) && ((g_keepmask[p >> 6] >> (p & 63)) & 1ull);
    int orig = g_order[p];
    float4 b = *(const float4*)&g_boxes[orig * 4];
    float s = g_scores[orig];
    float k = keep ? 1.0f : 0.0f;
    out[orig * 5 + 0] = b.x * k;
    out[orig * 5 + 1] = b.y * k;
    out[orig * 5 + 2] = b.z * k;
    out[orig * 5 + 3] = b.w * k;
    out[orig * 5 + 4] = s * k;
}

// ---------------- host launcher ----------------
extern "C" void kernel_launch(void* const* d_in, const int* in_sizes, int n_in,
                              void* d_out, int out_size) {
    const float* feat = (const float*)d_in[0];
    const float* w1   = (const float*)d_in[1];
    const float* b1   = (const float*)d_in[2];
    const float* w2   = (const float*)d_in[3];
    const float* b2   = (const float*)d_in[4];
    const float* w3   = (const float*)d_in[5];
    const float* b3   = (const float*)d_in[6];
    float* out = (float*)d_out;

    k_prep<<<PREP_BLOCKS, 256>>>(w1, feat);
    k_gemm<<<dim3(C_MID / 128, NPIX / 128, KSPLIT), 256>>>();
    k_heads<<<NPIX / 8, 256>>>(b1, w2, b2, w3, b3);
    k_rank<<<NBOX / 64, 256>>>();
    k_mask<<<NBOX / 64, 256>>>();
    k_nms<<<1, 256>>>();
    k_out<<<NBOX / 256, 256>>>(out);
}